// round 15
// baseline (speedup 1.0000x reference)
#include <cuda_runtime.h>
#include <cuda_fp16.h>
#include <cstdint>

// ======================= problem constants =======================
// B=128, T=1024, M=512 (GEMM N), P=256, K=512, rows = B*T = 131072
static constexpr int NB      = 128;
static constexpr int TLEN    = 1024;
static constexpr int MDIM    = 512;    // N of GEMM
static constexpr int KDIM    = 512;    // inner dim
static constexpr int MTILE   = 128;    // rows per CTA
static constexpr int NCHUNK  = 256;    // N per chunk (acc-resident)
static constexpr int NCHUNKS = MDIM / NCHUNK;    // 2
static constexpr int KSEG    = 32;     // K per B buffer / A slice
static constexpr int KSEGS   = KDIM / KSEG;      // 16
static constexpr int NITER   = NCHUNKS * KSEGS;  // 32

// padded strides (halves): rotate bank groups -> conflict-free ldmatrix
static constexpr int APAD  = 520;      // 1040 B/row
static constexpr int BPAD  = 40;       // 80 B/row (32k*2B + 16B pad)

static constexpr int SMEM_A_BYTES    = MTILE * APAD * 2;     // 133120
static constexpr int SMEM_BBUF_BYTES = NCHUNK * BPAD * 2;    // 20480
static constexpr int NBUF = 3;
static constexpr int DYN_SMEM = SMEM_A_BYTES + NBUF * SMEM_BBUF_BYTES;  // 194560

// ======================= scratch (device globals; no allocs) =======================
__device__ float g_wq[NB * MDIM];                    // wq[b][n]
__device__ __align__(16) __half g_U16[MDIM * KDIM];  // U_d fp16 [n][k]

// ======================= helpers =======================
__device__ __forceinline__ uint32_t smem_u32(const void* p) {
    return (uint32_t)__cvta_generic_to_shared(p);
}
__device__ __forceinline__ uint32_t pack_h2(float a, float b) {
    __half2 h = __floats2half2_rn(a, b);
    return *reinterpret_cast<uint32_t*>(&h);
}
__device__ __forceinline__ void ldsm_x4(uint32_t addr, uint32_t& r0, uint32_t& r1,
                                        uint32_t& r2, uint32_t& r3) {
    asm volatile("ldmatrix.sync.aligned.m8n8.x4.shared.b16 {%0,%1,%2,%3}, [%4];"
                 : "=r"(r0), "=r"(r1), "=r"(r2), "=r"(r3) : "r"(addr));
}
__device__ __forceinline__ void mma16816(float* c, const uint32_t* a,
                                         uint32_t b0, uint32_t b1) {
    asm volatile(
        "mma.sync.aligned.m16n8k16.row.col.f32.f16.f16.f32 "
        "{%0,%1,%2,%3}, {%4,%5,%6,%7}, {%8,%9}, {%0,%1,%2,%3};"
        : "+f"(c[0]), "+f"(c[1]), "+f"(c[2]), "+f"(c[3])
        : "r"(a[0]), "r"(a[1]), "r"(a[2]), "r"(a[3]), "r"(b0), "r"(b1));
}
__device__ __forceinline__ void cp_async16(uint32_t dst, const void* src) {
    asm volatile("cp.async.cg.shared.global [%0], [%1], 16;" :: "r"(dst), "l"(src));
}
__device__ __forceinline__ void cp_commit() {
    asm volatile("cp.async.commit_group;" ::: "memory");
}
__device__ __forceinline__ void cp_wait1() {
    asm volatile("cp.async.wait_group 1;" ::: "memory");
}
__device__ __forceinline__ void cp_wait0() {
    asm volatile("cp.async.wait_group 0;" ::: "memory");
}
// tanh(x) = 1 - 2/(e^{2x}+1): 2 MUFU, rel err ~1e-6
__device__ __forceinline__ float fast_tanh(float x) {
    float e = __expf(x + x);
    return 1.0f - __fdividef(2.0f, e + 1.0f);
}

// ======================= kernel 1: fused prep (512 blocks, 2 barriers) =======================
// blocks 0..255  : wq[b][2nb..2nb+2) -- W rows staged once, q read direct (L2)
// blocks 256..511: U_d fp32 -> fp16, single exact pass (65536 float4)
__global__ void __launch_bounds__(256, 1) prep_kernel(const float* __restrict__ dt,
                                                      const float* __restrict__ st,
                                                      const float* __restrict__ Wd,
                                                      const float* __restrict__ Ud) {
    const int t = threadIdx.x;
    if (blockIdx.x < 256) {
        // ---- wq: 2 n-rows per block ----
        __shared__ float Ws[2 * KDIM];            // 4 KB
        __shared__ float part[2][NB][2];          // [c-half][b][n-pair], 2 KB
        const int nbase = blockIdx.x * 2;
        // stage both W rows: 1024 floats = 256 float4, one per thread
        reinterpret_cast<float4*>(Ws)[t] =
            reinterpret_cast<const float4*>(Wd + (size_t)nbase * KDIM)[t];
        __syncthreads();

        const int b  = t & 127;
        const int jh = t >> 7;                    // c-half: 0 -> dt, 1 -> st
        const float4* qsrc = reinterpret_cast<const float4*>((jh ? st : dt) + b * 256);
        const float4* w0 = reinterpret_cast<const float4*>(Ws + jh * 256);
        const float4* w1 = reinterpret_cast<const float4*>(Ws + KDIM + jh * 256);
        float a0 = 0.f, a1 = 0.f;
#pragma unroll 8
        for (int c4 = 0; c4 < 64; c4++) {
            float4 q = qsrc[c4];
            float4 x = w0[c4];
            float4 y = w1[c4];
            a0 = fmaf(q.x, x.x, a0); a0 = fmaf(q.y, x.y, a0);
            a0 = fmaf(q.z, x.z, a0); a0 = fmaf(q.w, x.w, a0);
            a1 = fmaf(q.x, y.x, a1); a1 = fmaf(q.y, y.y, a1);
            a1 = fmaf(q.z, y.z, a1); a1 = fmaf(q.w, y.w, a1);
        }
        part[jh][b][0] = a0;
        part[jh][b][1] = a1;
        __syncthreads();
        if (t < NB) {
            g_wq[t * MDIM + nbase]     = part[0][t][0] + part[1][t][0];
            g_wq[t * MDIM + nbase + 1] = part[0][t][1] + part[1][t][1];
        }
    } else {
        // ---- U16: exactly 65536 float4 over 256 blocks x 256 threads ----
        const int i = (blockIdx.x - 256) * 256 + t;
        float4 f = reinterpret_cast<const float4*>(Ud)[i];
        uint2 u;
        u.x = pack_h2(f.x, f.y);
        u.y = pack_h2(f.z, f.w);
        reinterpret_cast<uint2*>(g_U16)[i] = u;
    }
}

// ======================= dummy kernels: ncu slot steering =======================
__global__ void dummy_kernel() {}
__global__ void dummy_kernel2() {}

// ======================= kernel 3: fused GEMM(HMMA) + tanh + v-dot (R9) =======================
// grid = 1024 CTAs (128 rows each), 512 threads (16 warps), 1 CTA/SM.
// warp w: rowgrp = w>>2 (32 rows), ngrp = w&3 (64 n within a 256-n chunk)
__global__ void __launch_bounds__(512, 1) attn_gemm_kernel(const float* __restrict__ H,
                                                           const float* __restrict__ vd,
                                                           float* __restrict__ out) {
    extern __shared__ __align__(16) char dsm[];
    __half* smemA = reinterpret_cast<__half*>(dsm);
    char*   smemB = dsm + SMEM_A_BYTES;

    __shared__ float wq_s[MDIM];
    __shared__ float v_s[MDIM];
    __shared__ float score4[4][MTILE];

    const int tid  = threadIdx.x;
    const int wid  = tid >> 5;
    const int lane = tid & 31;
    const int blk  = blockIdx.x;
    const int batch = blk >> 3;
    const size_t r0 = (size_t)blk * MTILE;

    for (int i = tid; i < MDIM; i += 512) {
        wq_s[i] = g_wq[batch * MDIM + i];
        v_s[i]  = vd[i];
    }

    const uint32_t bbuf0 = smem_u32(smemB);

    // ---- issue B for iters 0 and 1 (two groups; bufs 0 and 1) ----
#pragma unroll
    for (int j = 0; j < 2; j++) {
        const uint32_t dst = bbuf0 + (uint32_t)(j * SMEM_BBUF_BYTES);
#pragma unroll
        for (int it = 0; it < 2; it++) {
            int idx = tid + it * 512;
            int n = idx >> 2, kg = idx & 3;
            cp_async16(dst + (uint32_t)(n * 80 + kg * 16),
                       (const char*)g_U16 + n * 1024 + j * 64 + kg * 16);
        }
        cp_commit();
    }

    // ---- A conversion: 16 slices of 32 k; thread: row = tid>>2, 8 k at (tid&3)*8 ----
    const int arow = tid >> 2;
    const int akq  = (tid & 3) * 8;
    const float* aSrc = H + (r0 + (size_t)arow) * KDIM + akq;
    __half* aDst = smemA + arow * APAD + akq;

    float4 rA0, rA1;
    {   // store slice 0, load slice 1 into regs
        const float4* s0 = reinterpret_cast<const float4*>(aSrc);
        rA0 = s0[0]; rA1 = s0[1];
        uint4 u;
        u.x = pack_h2(rA0.x, rA0.y); u.y = pack_h2(rA0.z, rA0.w);
        u.z = pack_h2(rA1.x, rA1.y); u.w = pack_h2(rA1.z, rA1.w);
        *reinterpret_cast<uint4*>(aDst) = u;
        const float4* s1 = reinterpret_cast<const float4*>(aSrc + KSEG);
        rA0 = s1[0]; rA1 = s1[1];
    }

    // ---- per-lane ldmatrix addressing ----
    const int sub = lane >> 3;      // 8x8 tile index within x4
    const int l8  = lane & 7;
    const int rowgrp = wid >> 2;    // 4 rowgrps x 32 rows
    const int ngrp   = wid & 3;     // 4 ngrps x 64 n
    const int rbase  = rowgrp * 32;

    // A x4 tiles: t0 r0-7/k0-7, t1 r8-15/k0-7, t2 r0-7/k8-15, t3 r8-15/k8-15
    const uint32_t aAddr0 = smem_u32(smemA) +
        (uint32_t)(((rbase + (sub & 1) * 8 + l8) * APAD + (sub >> 1) * 8) * 2);
    const uint32_t aAddr1 = aAddr0 + (uint32_t)(16 * APAD * 2);
    // B x4 tiles: t0 n0-7/k0-7, t1 n0-7/k8-15, t2 n8-15/k0-7, t3 n8-15/k8-15
    const uint32_t bOff = (uint32_t)((ngrp * 64 + (sub >> 1) * 8 + l8) * 80 + (sub & 1) * 16);

    const int qn = (lane & 3) * 2;
    float s[4] = {0.0f, 0.0f, 0.0f, 0.0f};
    float acc[2][8][4];

    for (int i = 0; i < NITER; i++) {
        const int kseg  = i & 15;
        const int chunk = i >> 4;
        if (kseg == 0) {
#pragma unroll
            for (int mt = 0; mt < 2; mt++)
#pragma unroll
                for (int j = 0; j < 8; j++)
#pragma unroll
                    for (int q = 0; q < 4; q++) acc[mt][j][q] = 0.0f;
        }

        // ---- wait for group i (pending: g_i, g_{i+1}) then ONE barrier ----
        if (i + 1 < NITER) cp_wait1(); else cp_wait0();
        __syncthreads();
        // barrier also proves compute(i-1) done -> buf[(i+2)%3] = buf[(i-1)%3] is free

        if (i + 2 < NITER) {
            const int j = i + 2;
            const int nb_g = (j >> 4) * NCHUNK;
            const int ksb  = (j & 15) * 64;
            const uint32_t dst = bbuf0 + (uint32_t)((j % 3) * SMEM_BBUF_BYTES);
#pragma unroll
            for (int it = 0; it < 2; it++) {
                int idx = tid + it * 512;
                int n = idx >> 2, kg = idx & 3;
                cp_async16(dst + (uint32_t)(n * 80 + kg * 16),
                           (const char*)g_U16 + (size_t)(nb_g + n) * 1024 + ksb + kg * 16);
            }
            cp_commit();
        }

        // ---- A pipeline during chunk 0: store slice i+1, load slice i+2 ----
        if (i < 15) {
            uint4 u;
            u.x = pack_h2(rA0.x, rA0.y); u.y = pack_h2(rA0.z, rA0.w);
            u.z = pack_h2(rA1.x, rA1.y); u.w = pack_h2(rA1.z, rA1.w);
            *reinterpret_cast<uint4*>(aDst + (i + 1) * KSEG) = u;
            if (i + 2 < 16) {
                const float4* sN = reinterpret_cast<const float4*>(aSrc + (i + 2) * KSEG);
                rA0 = sN[0]; rA1 = sN[1];
            }
        }

        // ---- compute iter i: 2 k16-steps ----
        const uint32_t bA = bbuf0 + (uint32_t)((i % 3) * SMEM_BBUF_BYTES) + bOff;
        const uint32_t aK = (uint32_t)(kseg * 64);   // kseg*32k*2B

#pragma unroll
        for (int ks = 0; ks < 2; ks++) {
            uint32_t af[2][4];
            ldsm_x4(aAddr0 + aK + ks * 32, af[0][0], af[0][1], af[0][2], af[0][3]);
            ldsm_x4(aAddr1 + aK + ks * 32, af[1][0], af[1][1], af[1][2], af[1][3]);
            uint32_t bf[4][4];
#pragma unroll
            for (int nb = 0; nb < 4; nb++)
                ldsm_x4(bA + nb * (16 * 80) + ks * 32,
                        bf[nb][0], bf[nb][1], bf[nb][2], bf[nb][3]);
#pragma unroll
            for (int mt = 0; mt < 2; mt++)
#pragma unroll
                for (int nb = 0; nb < 4; nb++) {
                    mma16816(acc[mt][nb * 2],     af[mt], bf[nb][0], bf[nb][1]);
                    mma16816(acc[mt][nb * 2 + 1], af[mt], bf[nb][2], bf[nb][3]);
                }
        }

        if (kseg == 15) {
            // ---- fused epilogue for this 256-n chunk ----
            const int nbase = chunk * NCHUNK + ngrp * 64;
#pragma unroll
            for (int mt = 0; mt < 2; mt++)
#pragma unroll
                for (int j = 0; j < 8; j++) {
                    int n = nbase + (j >> 1) * 16 + (j & 1) * 8 + qn;
                    float w0 = wq_s[n], w1 = wq_s[n + 1];
                    float v0 = v_s[n],  v1 = v_s[n + 1];
                    s[0 + mt * 2] = fmaf(v0, fast_tanh(w0 + acc[mt][j][0]), s[0 + mt * 2]);
                    s[0 + mt * 2] = fmaf(v1, fast_tanh(w1 + acc[mt][j][1]), s[0 + mt * 2]);
                    s[1 + mt * 2] = fmaf(v0, fast_tanh(w0 + acc[mt][j][2]), s[1 + mt * 2]);
                    s[1 + mt * 2] = fmaf(v1, fast_tanh(w1 + acc[mt][j][3]), s[1 + mt * 2]);
                }
        }
    }

    // ---- final reduction: quad shuffle + per-ngrp arrays ----
#pragma unroll
    for (int q = 0; q < 4; q++) {
        s[q] += __shfl_xor_sync(0xffffffffu, s[q], 1);
        s[q] += __shfl_xor_sync(0xffffffffu, s[q], 2);
    }
    if ((lane & 3) == 0) {
        const int rr = rbase + (lane >> 2);
        score4[ngrp][rr]      = s[0];
        score4[ngrp][rr + 8]  = s[1];
        score4[ngrp][rr + 16] = s[2];
        score4[ngrp][rr + 24] = s[3];
    }
    __syncthreads();
    if (tid < MTILE)
        out[r0 + tid] = (score4[0][tid] + score4[1][tid]) + (score4[2][tid] + score4[3][tid]);
}

// ======================= kernel 4: softmax over T, in-place =======================
__global__ void __launch_bounds__(256, 1) softmax_kernel(float* __restrict__ out) {
    __shared__ float red[256];
    float* p = out + (size_t)blockIdx.x * TLEN;
    int tid = threadIdx.x;
    float v[4];
    float m = -1e30f;
#pragma unroll
    for (int j = 0; j < 4; j++) { v[j] = p[tid + j * 256]; m = fmaxf(m, v[j]); }
    red[tid] = m; __syncthreads();
    for (int s = 128; s > 0; s >>= 1) {
        if (tid < s) red[tid] = fmaxf(red[tid], red[tid + s]);
        __syncthreads();
    }
    float mx = red[0];
    __syncthreads();
    float sum = 0.0f;
#pragma unroll
    for (int j = 0; j < 4; j++) { v[j] = __expf(v[j] - mx); sum += v[j]; }
    red[tid] = sum; __syncthreads();
    for (int s = 128; s > 0; s >>= 1) {
        if (tid < s) red[tid] += red[tid + s];
        __syncthreads();
    }
    float inv = 1.0f / red[0];
#pragma unroll
    for (int j = 0; j < 4; j++) p[tid + j * 256] = v[j] * inv;
}

// ======================= launch =======================
extern "C" void kernel_launch(void* const* d_in, const int* in_sizes, int n_in,
                              void* d_out, int out_size) {
    const float *dt = nullptr, *st = nullptr, *H = nullptr;
    const float *W = nullptr, *U = nullptr, *v = nullptr;
    int c32768 = 0, c262144 = 0;
    for (int i = 0; i < n_in; i++) {
        int s = in_sizes[i];
        if (s == 32768)          { if (c32768++ == 0) dt = (const float*)d_in[i]; else st = (const float*)d_in[i]; }
        else if (s == 67108864)  { H = (const float*)d_in[i]; }
        else if (s == 262144)    { if (c262144++ == 0) W = (const float*)d_in[i]; else U = (const float*)d_in[i]; }
        else if (s == 512)       { v = (const float*)d_in[i]; }
    }
    float* out = (float*)d_out;

    cudaFuncSetAttribute(attn_gemm_kernel, cudaFuncAttributeMaxDynamicSharedMemorySize, DYN_SMEM);

    prep_kernel<<<512, 256>>>(dt, st, W, U);   // abs idx 2
    dummy_kernel<<<1, 32>>>();                 // 3
    dummy_kernel2<<<1, 32>>>();                // 4
    attn_gemm_kernel<<<1024, 512, DYN_SMEM>>>(H, v, out);   // 5 <- ncu -s 5
    softmax_kernel<<<128, 256>>>(out);
}

// round 16
// speedup vs baseline: 1.0685x; 1.0685x over previous
#include <cuda_runtime.h>
#include <cuda_fp16.h>
#include <cstdint>

// ======================= problem constants =======================
// B=128, T=1024, M=512 (GEMM N), P=256, K=512, rows = B*T = 131072
static constexpr int NB      = 128;
static constexpr int TLEN    = 1024;
static constexpr int MDIM    = 512;    // N of GEMM
static constexpr int KDIM    = 512;    // inner dim
static constexpr int MTILE   = 128;    // rows per CTA
static constexpr int NCHUNK  = 256;    // N per chunk (acc-resident)
static constexpr int NCHUNKS = MDIM / NCHUNK;    // 2
static constexpr int KSEG    = 32;     // K per B buffer / A slice
static constexpr int KSEGS   = KDIM / KSEG;      // 16
static constexpr int NITER   = NCHUNKS * KSEGS;  // 32

// padded strides (halves): rotate bank groups -> conflict-free ldmatrix
static constexpr int APAD  = 520;      // 1040 B/row
static constexpr int BPAD  = 40;       // 80 B/row (32k*2B + 16B pad)

static constexpr int SMEM_A_BYTES    = MTILE * APAD * 2;     // 133120
static constexpr int SMEM_BBUF_BYTES = NCHUNK * BPAD * 2;    // 20480
static constexpr int NBUF = 3;
static constexpr int DYN_SMEM = SMEM_A_BYTES + NBUF * SMEM_BBUF_BYTES;  // 194560

// ======================= scratch (device globals; no allocs) =======================
__device__ float g_wq[NB * MDIM];                    // wq[b][n]
__device__ __align__(16) __half g_U16[MDIM * KDIM];  // U_d fp16 [n][k]

// ======================= helpers =======================
__device__ __forceinline__ uint32_t smem_u32(const void* p) {
    return (uint32_t)__cvta_generic_to_shared(p);
}
__device__ __forceinline__ uint32_t pack_h2(float a, float b) {
    __half2 h = __floats2half2_rn(a, b);
    return *reinterpret_cast<uint32_t*>(&h);
}
__device__ __forceinline__ void ldsm_x4(uint32_t addr, uint32_t& r0, uint32_t& r1,
                                        uint32_t& r2, uint32_t& r3) {
    asm volatile("ldmatrix.sync.aligned.m8n8.x4.shared.b16 {%0,%1,%2,%3}, [%4];"
                 : "=r"(r0), "=r"(r1), "=r"(r2), "=r"(r3) : "r"(addr));
}
__device__ __forceinline__ void mma16816(float* c, const uint32_t* a,
                                         uint32_t b0, uint32_t b1) {
    asm volatile(
        "mma.sync.aligned.m16n8k16.row.col.f32.f16.f16.f32 "
        "{%0,%1,%2,%3}, {%4,%5,%6,%7}, {%8,%9}, {%0,%1,%2,%3};"
        : "+f"(c[0]), "+f"(c[1]), "+f"(c[2]), "+f"(c[3])
        : "r"(a[0]), "r"(a[1]), "r"(a[2]), "r"(a[3]), "r"(b0), "r"(b1));
}
__device__ __forceinline__ void cp_async16(uint32_t dst, const void* src) {
    asm volatile("cp.async.cg.shared.global [%0], [%1], 16;" :: "r"(dst), "l"(src));
}
__device__ __forceinline__ void cp_commit() {
    asm volatile("cp.async.commit_group;" ::: "memory");
}
__device__ __forceinline__ void cp_wait1() {
    asm volatile("cp.async.wait_group 1;" ::: "memory");
}
__device__ __forceinline__ void cp_wait0() {
    asm volatile("cp.async.wait_group 0;" ::: "memory");
}
// tanh(x) = 1 - 2/(e^{2x}+1): 2 MUFU, rel err ~1e-6
__device__ __forceinline__ float fast_tanh(float x) {
    float e = __expf(x + x);
    return 1.0f - __fdividef(2.0f, e + 1.0f);
}

// ======================= kernel 1: fused prep (1280 blocks, coalesced) =======================
// blocks 0..1023   : wq -- 64 n-tiles(8) x 16 b-groups(8); warp = one b, lanes along c
// blocks 1024..1279: U_d fp32 -> fp16, single exact pass (65536 float4)
__global__ void __launch_bounds__(256, 1) prep_kernel(const float* __restrict__ dt,
                                                      const float* __restrict__ st,
                                                      const float* __restrict__ Wd,
                                                      const float* __restrict__ Ud) {
    const int t = threadIdx.x;
    if (blockIdx.x < 1024) {
        __shared__ float4 Ws4[1024];              // 8 W rows x 512 floats = 16 KB
        const int n0   = (blockIdx.x >> 4) * 8;
        const int b    = (blockIdx.x & 15) * 8 + (t >> 5);
        const int lane = t & 31;
        // stage W rows n0..n0+8 (coalesced float4)
#pragma unroll
        for (int j = 0; j < 4; j++)
            Ws4[t + j * 256] =
                reinterpret_cast<const float4*>(Wd + (size_t)n0 * KDIM)[t + j * 256];
        __syncthreads();

        // q[b]: 4 coalesced float4 per lane (lanes along c -> nL=1)
        float4 q[4];
#pragma unroll
        for (int j = 0; j < 2; j++)
            q[j] = reinterpret_cast<const float4*>(dt + b * 256)[lane + 32 * j];
#pragma unroll
        for (int j = 0; j < 2; j++)
            q[2 + j] = reinterpret_cast<const float4*>(st + b * 256)[lane + 32 * j];

        float acc[8] = {0.f, 0.f, 0.f, 0.f, 0.f, 0.f, 0.f, 0.f};
#pragma unroll
        for (int n = 0; n < 8; n++)
#pragma unroll
            for (int j = 0; j < 4; j++) {
                float4 w = Ws4[n * 128 + lane + 32 * j];
                acc[n] = fmaf(q[j].x, w.x, acc[n]);
                acc[n] = fmaf(q[j].y, w.y, acc[n]);
                acc[n] = fmaf(q[j].z, w.z, acc[n]);
                acc[n] = fmaf(q[j].w, w.w, acc[n]);
            }
        // butterfly reduce over lanes (c partition)
#pragma unroll
        for (int off = 16; off > 0; off >>= 1)
#pragma unroll
            for (int n = 0; n < 8; n++)
                acc[n] += __shfl_xor_sync(0xffffffffu, acc[n], off);
        if (lane == 0) {
#pragma unroll
            for (int n = 0; n < 8; n++)
                g_wq[b * MDIM + n0 + n] = acc[n];
        }
    } else {
        // ---- U16: exactly 65536 float4 over 256 blocks x 256 threads ----
        const int i = (blockIdx.x - 1024) * 256 + t;
        float4 f = reinterpret_cast<const float4*>(Ud)[i];
        uint2 u;
        u.x = pack_h2(f.x, f.y);
        u.y = pack_h2(f.z, f.w);
        reinterpret_cast<uint2*>(g_U16)[i] = u;
    }
}

// ======================= dummy kernels: ncu slot steering =======================
__global__ void dummy_kernel() {}
__global__ void dummy_kernel2() {}
__global__ void dummy_kernel3() {}

// ======================= kernel 3: fused GEMM(HMMA) + tanh + v-dot (R9) =======================
// grid = 1024 CTAs (128 rows each), 512 threads (16 warps), 1 CTA/SM.
// warp w: rowgrp = w>>2 (32 rows), ngrp = w&3 (64 n within a 256-n chunk)
__global__ void __launch_bounds__(512, 1) attn_gemm_kernel(const float* __restrict__ H,
                                                           const float* __restrict__ vd,
                                                           float* __restrict__ out) {
    extern __shared__ __align__(16) char dsm[];
    __half* smemA = reinterpret_cast<__half*>(dsm);
    char*   smemB = dsm + SMEM_A_BYTES;

    __shared__ float wq_s[MDIM];
    __shared__ float v_s[MDIM];
    __shared__ float score4[4][MTILE];

    const int tid  = threadIdx.x;
    const int wid  = tid >> 5;
    const int lane = tid & 31;
    const int blk  = blockIdx.x;
    const int batch = blk >> 3;
    const size_t r0 = (size_t)blk * MTILE;

    for (int i = tid; i < MDIM; i += 512) {
        wq_s[i] = g_wq[batch * MDIM + i];
        v_s[i]  = vd[i];
    }

    const uint32_t bbuf0 = smem_u32(smemB);

    // ---- issue B for iters 0 and 1 (two groups; bufs 0 and 1) ----
#pragma unroll
    for (int j = 0; j < 2; j++) {
        const uint32_t dst = bbuf0 + (uint32_t)(j * SMEM_BBUF_BYTES);
#pragma unroll
        for (int it = 0; it < 2; it++) {
            int idx = tid + it * 512;
            int n = idx >> 2, kg = idx & 3;
            cp_async16(dst + (uint32_t)(n * 80 + kg * 16),
                       (const char*)g_U16 + n * 1024 + j * 64 + kg * 16);
        }
        cp_commit();
    }

    // ---- A conversion: 16 slices of 32 k; thread: row = tid>>2, 8 k at (tid&3)*8 ----
    const int arow = tid >> 2;
    const int akq  = (tid & 3) * 8;
    const float* aSrc = H + (r0 + (size_t)arow) * KDIM + akq;
    __half* aDst = smemA + arow * APAD + akq;

    float4 rA0, rA1;
    {   // store slice 0, load slice 1 into regs
        const float4* s0 = reinterpret_cast<const float4*>(aSrc);
        rA0 = s0[0]; rA1 = s0[1];
        uint4 u;
        u.x = pack_h2(rA0.x, rA0.y); u.y = pack_h2(rA0.z, rA0.w);
        u.z = pack_h2(rA1.x, rA1.y); u.w = pack_h2(rA1.z, rA1.w);
        *reinterpret_cast<uint4*>(aDst) = u;
        const float4* s1 = reinterpret_cast<const float4*>(aSrc + KSEG);
        rA0 = s1[0]; rA1 = s1[1];
    }

    // ---- per-lane ldmatrix addressing ----
    const int sub = lane >> 3;      // 8x8 tile index within x4
    const int l8  = lane & 7;
    const int rowgrp = wid >> 2;    // 4 rowgrps x 32 rows
    const int ngrp   = wid & 3;     // 4 ngrps x 64 n
    const int rbase  = rowgrp * 32;

    // A x4 tiles: t0 r0-7/k0-7, t1 r8-15/k0-7, t2 r0-7/k8-15, t3 r8-15/k8-15
    const uint32_t aAddr0 = smem_u32(smemA) +
        (uint32_t)(((rbase + (sub & 1) * 8 + l8) * APAD + (sub >> 1) * 8) * 2);
    const uint32_t aAddr1 = aAddr0 + (uint32_t)(16 * APAD * 2);
    // B x4 tiles: t0 n0-7/k0-7, t1 n0-7/k8-15, t2 n8-15/k0-7, t3 n8-15/k8-15
    const uint32_t bOff = (uint32_t)((ngrp * 64 + (sub >> 1) * 8 + l8) * 80 + (sub & 1) * 16);

    const int qn = (lane & 3) * 2;
    float s[4] = {0.0f, 0.0f, 0.0f, 0.0f};
    float acc[2][8][4];

    for (int i = 0; i < NITER; i++) {
        const int kseg  = i & 15;
        const int chunk = i >> 4;
        if (kseg == 0) {
#pragma unroll
            for (int mt = 0; mt < 2; mt++)
#pragma unroll
                for (int j = 0; j < 8; j++)
#pragma unroll
                    for (int q = 0; q < 4; q++) acc[mt][j][q] = 0.0f;
        }

        // ---- wait for group i (pending: g_i, g_{i+1}) then ONE barrier ----
        if (i + 1 < NITER) cp_wait1(); else cp_wait0();
        __syncthreads();
        // barrier also proves compute(i-1) done -> buf[(i+2)%3] = buf[(i-1)%3] is free

        if (i + 2 < NITER) {
            const int j = i + 2;
            const int nb_g = (j >> 4) * NCHUNK;
            const int ksb  = (j & 15) * 64;
            const uint32_t dst = bbuf0 + (uint32_t)((j % 3) * SMEM_BBUF_BYTES);
#pragma unroll
            for (int it = 0; it < 2; it++) {
                int idx = tid + it * 512;
                int n = idx >> 2, kg = idx & 3;
                cp_async16(dst + (uint32_t)(n * 80 + kg * 16),
                           (const char*)g_U16 + (size_t)(nb_g + n) * 1024 + ksb + kg * 16);
            }
            cp_commit();
        }

        // ---- A pipeline during chunk 0: store slice i+1, load slice i+2 ----
        if (i < 15) {
            uint4 u;
            u.x = pack_h2(rA0.x, rA0.y); u.y = pack_h2(rA0.z, rA0.w);
            u.z = pack_h2(rA1.x, rA1.y); u.w = pack_h2(rA1.z, rA1.w);
            *reinterpret_cast<uint4*>(aDst + (i + 1) * KSEG) = u;
            if (i + 2 < 16) {
                const float4* sN = reinterpret_cast<const float4*>(aSrc + (i + 2) * KSEG);
                rA0 = sN[0]; rA1 = sN[1];
            }
        }

        // ---- compute iter i: 2 k16-steps ----
        const uint32_t bA = bbuf0 + (uint32_t)((i % 3) * SMEM_BBUF_BYTES) + bOff;
        const uint32_t aK = (uint32_t)(kseg * 64);   // kseg*32k*2B

#pragma unroll
        for (int ks = 0; ks < 2; ks++) {
            uint32_t af[2][4];
            ldsm_x4(aAddr0 + aK + ks * 32, af[0][0], af[0][1], af[0][2], af[0][3]);
            ldsm_x4(aAddr1 + aK + ks * 32, af[1][0], af[1][1], af[1][2], af[1][3]);
            uint32_t bf[4][4];
#pragma unroll
            for (int nb = 0; nb < 4; nb++)
                ldsm_x4(bA + nb * (16 * 80) + ks * 32,
                        bf[nb][0], bf[nb][1], bf[nb][2], bf[nb][3]);
#pragma unroll
            for (int mt = 0; mt < 2; mt++)
#pragma unroll
                for (int nb = 0; nb < 4; nb++) {
                    mma16816(acc[mt][nb * 2],     af[mt], bf[nb][0], bf[nb][1]);
                    mma16816(acc[mt][nb * 2 + 1], af[mt], bf[nb][2], bf[nb][3]);
                }
        }

        if (kseg == 15) {
            // ---- fused epilogue for this 256-n chunk ----
            const int nbase = chunk * NCHUNK + ngrp * 64;
#pragma unroll
            for (int mt = 0; mt < 2; mt++)
#pragma unroll
                for (int j = 0; j < 8; j++) {
                    int n = nbase + (j >> 1) * 16 + (j & 1) * 8 + qn;
                    float w0 = wq_s[n], w1 = wq_s[n + 1];
                    float v0 = v_s[n],  v1 = v_s[n + 1];
                    s[0 + mt * 2] = fmaf(v0, fast_tanh(w0 + acc[mt][j][0]), s[0 + mt * 2]);
                    s[0 + mt * 2] = fmaf(v1, fast_tanh(w1 + acc[mt][j][1]), s[0 + mt * 2]);
                    s[1 + mt * 2] = fmaf(v0, fast_tanh(w0 + acc[mt][j][2]), s[1 + mt * 2]);
                    s[1 + mt * 2] = fmaf(v1, fast_tanh(w1 + acc[mt][j][3]), s[1 + mt * 2]);
                }
        }
    }

    // ---- final reduction: quad shuffle + per-ngrp arrays ----
#pragma unroll
    for (int q = 0; q < 4; q++) {
        s[q] += __shfl_xor_sync(0xffffffffu, s[q], 1);
        s[q] += __shfl_xor_sync(0xffffffffu, s[q], 2);
    }
    if ((lane & 3) == 0) {
        const int rr = rbase + (lane >> 2);
        score4[ngrp][rr]      = s[0];
        score4[ngrp][rr + 8]  = s[1];
        score4[ngrp][rr + 16] = s[2];
        score4[ngrp][rr + 24] = s[3];
    }
    __syncthreads();
    if (tid < MTILE)
        out[r0 + tid] = (score4[0][tid] + score4[1][tid]) + (score4[2][tid] + score4[3][tid]);
}

// ======================= kernel 4: softmax over T, in-place =======================
__global__ void __launch_bounds__(256, 1) softmax_kernel(float* __restrict__ out) {
    __shared__ float red[256];
    float* p = out + (size_t)blockIdx.x * TLEN;
    int tid = threadIdx.x;
    float v[4];
    float m = -1e30f;
#pragma unroll
    for (int j = 0; j < 4; j++) { v[j] = p[tid + j * 256]; m = fmaxf(m, v[j]); }
    red[tid] = m; __syncthreads();
    for (int s = 128; s > 0; s >>= 1) {
        if (tid < s) red[tid] = fmaxf(red[tid], red[tid + s]);
        __syncthreads();
    }
    float mx = red[0];
    __syncthreads();
    float sum = 0.0f;
#pragma unroll
    for (int j = 0; j < 4; j++) { v[j] = __expf(v[j] - mx); sum += v[j]; }
    red[tid] = sum; __syncthreads();
    for (int s = 128; s > 0; s >>= 1) {
        if (tid < s) red[tid] += red[tid + s];
        __syncthreads();
    }
    float inv = 1.0f / red[0];
#pragma unroll
    for (int j = 0; j < 4; j++) p[tid + j * 256] = v[j] * inv;
}

// ======================= launch =======================
extern "C" void kernel_launch(void* const* d_in, const int* in_sizes, int n_in,
                              void* d_out, int out_size) {
    const float *dt = nullptr, *st = nullptr, *H = nullptr;
    const float *W = nullptr, *U = nullptr, *v = nullptr;
    int c32768 = 0, c262144 = 0;
    for (int i = 0; i < n_in; i++) {
        int s = in_sizes[i];
        if (s == 32768)          { if (c32768++ == 0) dt = (const float*)d_in[i]; else st = (const float*)d_in[i]; }
        else if (s == 67108864)  { H = (const float*)d_in[i]; }
        else if (s == 262144)    { if (c262144++ == 0) W = (const float*)d_in[i]; else U = (const float*)d_in[i]; }
        else if (s == 512)       { v = (const float*)d_in[i]; }
    }
    float* out = (float*)d_out;

    cudaFuncSetAttribute(attn_gemm_kernel, cudaFuncAttributeMaxDynamicSharedMemorySize, DYN_SMEM);

    dummy_kernel<<<1, 32>>>();                  // abs idx 2
    dummy_kernel2<<<1, 32>>>();                 // 3
    dummy_kernel3<<<1, 32>>>();                 // 4
    prep_kernel<<<1280, 256>>>(dt, st, W, U);   // 5 <- ncu -s 5 target this round
    attn_gemm_kernel<<<1024, 512, DYN_SMEM>>>(H, v, out);
    softmax_kernel<<<128, 256>>>(out);
}